// round 10
// baseline (speedup 1.0000x reference)
#include <cuda_runtime.h>
#include <cstdint>

// Problem constants
#define BB 64
#define HH 1024
#define II 512
#define MIN_TAU 1e-3f
#define LOG2E 1.4426950408889634f

// Tiling: 256 resident CTAs (single wave on 148 SMs x 2 CTAs).
// CTA = fixed o-group of 8 rows x 32 b-iterations.
// 8 consumer warps + 1 dedicated producer warp = 288 threads.
#define OW 8
#define NWARPS 9
#define BITERS 32
#define OGROUPS (HH / OW)       // 128
#define HALVES (BB / BITERS)    // 2
#define STAGES 3

// SMEM layout (dynamic): stage = 8 gumbel rows x 4KB (h_prev now via LDG).
#define ROW_BYTES (HH * 4)               // 4096
#define STAGE_BYTES (OW * ROW_BYTES)     // 32768
#define FULL_OFF (STAGES * STAGE_BYTES)  // 98304: per-ROW full barriers
#define EMPTY_OFF (FULL_OFF + STAGES * OW * 8)   // +192
#define SMEM_BYTES (EMPTY_OFF + STAGES * 8)      // 98520 -> 2 CTAs/SM

static __device__ __forceinline__ uint32_t s2u(const void* p) {
    uint32_t a;
    asm("{ .reg .u64 t; cvta.to.shared.u64 t, %1; cvt.u32.u64 %0, t; }"
        : "=r"(a) : "l"(p));
    return a;
}

static __device__ __forceinline__ void mbar_init(uint32_t mbar, uint32_t cnt) {
    asm volatile("mbarrier.init.shared.b64 [%0], %1;" :: "r"(mbar), "r"(cnt) : "memory");
}

static __device__ __forceinline__ void mbar_expect_tx(uint32_t mbar, uint32_t bytes) {
    asm volatile("mbarrier.arrive.expect_tx.shared.b64 _, [%0], %1;"
                 :: "r"(mbar), "r"(bytes) : "memory");
}

static __device__ __forceinline__ void mbar_arrive(uint32_t mbar) {
    asm volatile("mbarrier.arrive.release.cta.shared::cta.b64 _, [%0];"
                 :: "r"(mbar) : "memory");
}

static __device__ __forceinline__ void mbar_wait(uint32_t mbar, uint32_t parity) {
    uint32_t done;
    asm volatile(
        "{\n\t.reg .pred p;\n\t"
        "mbarrier.try_wait.parity.acquire.cta.shared::cta.b64 p, [%1], %2;\n\t"
        "selp.b32 %0, 1, 0, p;\n\t}"
        : "=r"(done) : "r"(mbar), "r"(parity) : "memory");
    if (!done) {
        asm volatile(
            "{\n\t.reg .pred P1;\n\t"
            "WL_%=:\n\t"
            "mbarrier.try_wait.parity.acquire.cta.shared::cta.b64 P1, [%0], %1, 0x989680;\n\t"
            "@P1 bra.uni WD_%=;\n\t"
            "bra.uni WL_%=;\n\t"
            "WD_%=:\n\t}"
            :: "r"(mbar), "r"(parity) : "memory");
    }
}

static __device__ __forceinline__ void bulk_copy(uint32_t dst_smem, const void* src,
                                                 uint32_t bytes, uint32_t mbar) {
    asm volatile(
        "cp.async.bulk.shared::cta.global.mbarrier::complete_tx::bytes [%0], [%1], %2, [%3];"
        :: "r"(dst_smem), "l"(src), "r"(bytes), "r"(mbar) : "memory");
}

static __device__ __forceinline__ void fence_async_smem() {
    asm volatile("fence.proxy.async.shared::cta;" ::: "memory");
}

static __device__ __forceinline__ float ex2(float x) {
    float y;
    asm("ex2.approx.ftz.f32 %0, %1;" : "=f"(y) : "f"(x));
    return y;
}

// Fused ReservoirRNNCell step — warp-specialized TMA pipeline with PER-ROW
// full barriers:
//   grid = 256 CTAs (one wave), 288 threads: warps 0-7 consume, warp 8
//   produces. 3-stage ring, stage = 8 x 4KB gumbel rows. The producer issues
//   8 INDEPENDENT 4KB bulk copies per stage, each completing its own row
//   barrier: consumer warp w unblocks the moment ITS row lands (not when the
//   whole 36KB stage lands, as in R9) -> warps self-stagger, smoothing
//   MUFU/LDS bursts. h_prev moved out of smem to LDG float4 (L2-resident,
//   front-batched MLP 8): smem traffic per CTA-iteration drops 100KB -> 64KB.
//   Empty barriers stay per-stage (8 arrivals); producer: wait empty
//   (acquire) -> fence.proxy.async -> 8x(expect_tx + copy).
// Softmax without max-subtraction is safe: logits bounded (~18.5);
// validated rel_err 3.4e-7 in R1-R9.
__global__ __launch_bounds__(288, 2) void reservoir_cell_kernel(
    const float* __restrict__ x_t,         // (B, I)
    const float* __restrict__ h_prev,      // (B, H)
    const float* __restrict__ W_ih,        // (H, I)
    const float* __restrict__ b_ih,        // (H,)
    const float* __restrict__ W_hh,        // (H, H)
    const float* __restrict__ temperature, // scalar
    const float* __restrict__ gumbel,      // (B, H, H)
    float* __restrict__ out)               // (B, H)
{
    extern __shared__ float smem[];
    const uint32_t smem_u = s2u(smem);
    const uint32_t fullb  = smem_u + FULL_OFF;    // [stage][row] 8B each
    const uint32_t emptyb = smem_u + EMPTY_OFF;   // [stage]

    const int og   = blockIdx.x & (OGROUPS - 1);   // 0..127
    const int half = blockIdx.x >> 7;              // 0..1
    const int b0 = half * BITERS;
    const int o0 = og * OW;

    const int tid  = threadIdx.x;
    const int w    = tid >> 5;
    const int lane = tid & 31;

    // ---- init barriers ----
    if (tid == 0) {
#pragma unroll
        for (int j = 0; j < STAGES; ++j) {
#pragma unroll
            for (int r = 0; r < OW; ++r)
                mbar_init(fullb + 8u * (j * OW + r), 1);
            mbar_init(emptyb + 8u * j, OW);   // one arrive per consumer warp
        }
    }
    __syncthreads();   // the ONLY block-wide sync

    // ================= PRODUCER WARP (w == 8) =================
    if (w == 8) {
        if (lane == 0) {
            int st = 0, rnd = 0;
            for (int f = 0; f < BITERS; ++f) {
                if (rnd >= 1) {
                    mbar_wait(emptyb + 8u * st, (rnd - 1) & 1);
                    fence_async_smem();
                }
                const float* gsrc = gumbel + ((size_t)(b0 + f) * HH + o0) * HH;
                const uint32_t dst = smem_u + st * STAGE_BYTES;
#pragma unroll
                for (int r = 0; r < OW; ++r) {
                    const uint32_t mb = fullb + 8u * (st * OW + r);
                    mbar_expect_tx(mb, ROW_BYTES);
                    bulk_copy(dst + r * ROW_BYTES, gsrc + (size_t)r * HH,
                              ROW_BYTES, mb);
                }
                if (++st == STAGES) { st = 0; ++rnd; }
            }
        }
        return;
    }

    // ================= CONSUMER WARPS (w == 0..7) =================
    const int o = o0 + w;

    // per-warp constants, loaded ONCE per 32 tiles (overlaps prologue TMA)
    const float inv_tau_l2e = LOG2E / fmaxf(temperature[0], MIN_TAU);
    const float bias = b_ih[o];

    const float4* __restrict__ whr = reinterpret_cast<const float4*>(W_hh + (size_t)o * HH);
    float4 wp[8];
#pragma unroll
    for (int k = 0; k < 8; ++k) {
        float4 v = whr[lane + 32 * k];
        v.x *= inv_tau_l2e; v.y *= inv_tau_l2e;
        v.z *= inv_tau_l2e; v.w *= inv_tau_l2e;
        wp[k] = v;
    }
    const float4* __restrict__ wir = reinterpret_cast<const float4*>(W_ih + (size_t)o * II);
    float4 wih[4];
#pragma unroll
    for (int k = 0; k < 4; ++k) wih[k] = wir[lane + 32 * k];

    // warp's smem row base per stage: stage st, row w
    const float* __restrict__ rowbase = smem + (size_t)w * HH;

    int st = 0;
    int parity = 0;   // round parity: r = i/STAGES, parity = r&1
    for (int i = 0; i < BITERS; ++i) {
        const int b = b0 + i;

        // front-batched global loads (L2/L1-resident): h_prev row (8x float4,
        // MLP 8) + x_t row (4x float4). These fill the wait latency.
        const float4* __restrict__ hr =
            reinterpret_cast<const float4*>(h_prev + (size_t)b * HH);
        float4 hv[8];
#pragma unroll
        for (int k = 0; k < 8; ++k) hv[k] = hr[lane + 32 * k];

        const float4* __restrict__ xr =
            reinterpret_cast<const float4*>(x_t + (size_t)b * II);
        float ic = 0.0f;
#pragma unroll
        for (int k = 0; k < 4; ++k) {
            const float4 xv = xr[lane + 32 * k];
            ic = fmaf(xv.x, wih[k].x, ic);
            ic = fmaf(xv.y, wih[k].y, ic);
            ic = fmaf(xv.z, wih[k].z, ic);
            ic = fmaf(xv.w, wih[k].w, ic);
        }

        // wait ONLY for this warp's 4KB row
        mbar_wait(fullb + 8u * (st * OW + w), parity);

        const float4* __restrict__ gs = reinterpret_cast<const float4*>(
            rowbase + (size_t)st * (STAGE_BYTES / 4));

        float s = 0.0f, t = 0.0f;
#pragma unroll
        for (int k = 0; k < 8; ++k) {
            const float4 g = gs[lane + 32 * k];
            const float4 h = hv[k];
            float e;
            e = ex2(fmaf(g.x, LOG2E, wp[k].x)); s += e; t = fmaf(e, h.x, t);
            e = ex2(fmaf(g.y, LOG2E, wp[k].y)); s += e; t = fmaf(e, h.y, t);
            e = ex2(fmaf(g.z, LOG2E, wp[k].z)); s += e; t = fmaf(e, h.z, t);
            e = ex2(fmaf(g.w, LOG2E, wp[k].w)); s += e; t = fmaf(e, h.w, t);
        }

        // row consumed into registers: signal the producer and move on.
        __syncwarp();
        if (lane == 0) mbar_arrive(emptyb + 8u * st);

        // warp reductions + output (overlaps the producer's refill)
#pragma unroll
        for (int off = 16; off > 0; off >>= 1) {
            s  += __shfl_xor_sync(0xffffffffu, s,  off);
            t  += __shfl_xor_sync(0xffffffffu, t,  off);
            ic += __shfl_xor_sync(0xffffffffu, ic, off);
        }
        if (lane == 0) {
            out[(size_t)b * HH + o] = tanhf(ic + bias + t / s);
        }

        if (++st == STAGES) { st = 0; parity ^= 1; }
    }
}

extern "C" void kernel_launch(void* const* d_in, const int* in_sizes, int n_in,
                              void* d_out, int out_size) {
    // metadata order: x_t, h_prev, W_ih, b_ih, W_hh, temperature, gumbel_noise
    const float* x_t    = (const float*)d_in[0];
    const float* h_prev = (const float*)d_in[1];
    const float* W_ih   = (const float*)d_in[2];
    const float* b_ih   = (const float*)d_in[3];
    const float* W_hh   = (const float*)d_in[4];
    const float* temp   = (const float*)d_in[5];
    const float* gum    = (const float*)d_in[6];
    float* out = (float*)d_out;

    static bool attr_set = false;
    if (!attr_set) {
        cudaFuncSetAttribute(reservoir_cell_kernel,
                             cudaFuncAttributeMaxDynamicSharedMemorySize, SMEM_BYTES);
        attr_set = true;
    }

    dim3 grid(OGROUPS * HALVES);   // 128 * 2 = 256 CTAs: one resident wave
    dim3 block(NWARPS * 32);       // 288 threads: 8 consumer + 1 producer warp
    reservoir_cell_kernel<<<grid, block, SMEM_BYTES>>>(
        x_t, h_prev, W_ih, b_ih, W_hh, temp, gum, out);
}

// round 11
// speedup vs baseline: 1.0020x; 1.0020x over previous
#include <cuda_runtime.h>
#include <cstdint>

// Problem constants
#define BB 64
#define HH 1024
#define II 512
#define MIN_TAU 1e-3f
#define LOG2E 1.4426950408889634f

// Tiling: 256 resident CTAs (single wave on 148 SMs x 2 CTAs).
// CTA = fixed o-group of 8 rows x 32 b-iterations.
// 8 consumer warps + 1 dedicated producer warp = 288 threads.
#define OW 8
#define NWARPS 9
#define BITERS 32
#define OGROUPS (HH / OW)       // 128
#define HALVES (BB / BITERS)    // 2
#define STAGES 3

// SMEM layout (dynamic): stage = 32KB gumbel tile ONLY (h_prev via LDG).
#define STAGE_BYTES (OW * HH * 4)        // 32768
#define FULL_OFF (STAGES * STAGE_BYTES)  // 98304
#define EMPTY_OFF (FULL_OFF + STAGES * 8)
#define SMEM_BYTES (EMPTY_OFF + STAGES * 8)  // 98352 -> 2 CTAs/SM

static __device__ __forceinline__ uint32_t s2u(const void* p) {
    uint32_t a;
    asm("{ .reg .u64 t; cvta.to.shared.u64 t, %1; cvt.u32.u64 %0, t; }"
        : "=r"(a) : "l"(p));
    return a;
}

static __device__ __forceinline__ void mbar_init(uint32_t mbar, uint32_t cnt) {
    asm volatile("mbarrier.init.shared.b64 [%0], %1;" :: "r"(mbar), "r"(cnt) : "memory");
}

static __device__ __forceinline__ void mbar_expect_tx(uint32_t mbar, uint32_t bytes) {
    asm volatile("mbarrier.arrive.expect_tx.shared.b64 _, [%0], %1;"
                 :: "r"(mbar), "r"(bytes) : "memory");
}

static __device__ __forceinline__ void mbar_arrive(uint32_t mbar) {
    asm volatile("mbarrier.arrive.release.cta.shared::cta.b64 _, [%0];"
                 :: "r"(mbar) : "memory");
}

static __device__ __forceinline__ void mbar_wait(uint32_t mbar, uint32_t parity) {
    uint32_t done;
    asm volatile(
        "{\n\t.reg .pred p;\n\t"
        "mbarrier.try_wait.parity.acquire.cta.shared::cta.b64 p, [%1], %2;\n\t"
        "selp.b32 %0, 1, 0, p;\n\t}"
        : "=r"(done) : "r"(mbar), "r"(parity) : "memory");
    if (!done) {
        asm volatile(
            "{\n\t.reg .pred P1;\n\t"
            "WL_%=:\n\t"
            "mbarrier.try_wait.parity.acquire.cta.shared::cta.b64 P1, [%0], %1, 0x989680;\n\t"
            "@P1 bra.uni WD_%=;\n\t"
            "bra.uni WL_%=;\n\t"
            "WD_%=:\n\t}"
            :: "r"(mbar), "r"(parity) : "memory");
    }
}

static __device__ __forceinline__ void bulk_copy(uint32_t dst_smem, const void* src,
                                                 uint32_t bytes, uint32_t mbar) {
    asm volatile(
        "cp.async.bulk.shared::cta.global.mbarrier::complete_tx::bytes [%0], [%1], %2, [%3];"
        :: "r"(dst_smem), "l"(src), "r"(bytes), "r"(mbar) : "memory");
}

static __device__ __forceinline__ void fence_async_smem() {
    asm volatile("fence.proxy.async.shared::cta;" ::: "memory");
}

static __device__ __forceinline__ float ex2(float x) {
    float y;
    asm("ex2.approx.ftz.f32 %0, %1;" : "=f"(y) : "f"(x));
    return y;
}

// Fused ReservoirRNNCell step — warp-specialized TMA pipeline (R9 skeleton):
//   grid = 256 CTAs (one wave at 2 CTAs/SM), 288 threads: warps 0-7 consume,
//   warp 8 produces. 3-stage ring; each fill is ONE 32KB cp.async.bulk of
//   gumbel[b, o0:o0+8, :] (the R9-proven granularity — 4KB copies regressed
//   hard in R4/R10). Per-stage full barrier (tx) + per-stage empty barrier
//   (8 consumer arrivals).
// R11 change vs R9: h_prev is NO LONGER in the TMA payload. Each consumer
//   front-batches 8x float4 LDGs of h_prev[b,:] (L2-resident, reused by 128
//   CTAs) BEFORE its full-wait, hiding the L2 latency under the wait. This
//   cuts smem port traffic per CTA-iteration from 100KB to 64KB and the TMA
//   payload from 36KB to 32KB.
// Softmax without max-subtraction is safe: logits bounded (~18.5);
// validated rel_err 3.4e-7 in R1-R10.
__global__ __launch_bounds__(288, 2) void reservoir_cell_kernel(
    const float* __restrict__ x_t,         // (B, I)
    const float* __restrict__ h_prev,      // (B, H)
    const float* __restrict__ W_ih,        // (H, I)
    const float* __restrict__ b_ih,        // (H,)
    const float* __restrict__ W_hh,        // (H, H)
    const float* __restrict__ temperature, // scalar
    const float* __restrict__ gumbel,      // (B, H, H)
    float* __restrict__ out)               // (B, H)
{
    extern __shared__ float smem[];
    const uint32_t smem_u = s2u(smem);
    const uint32_t fullb  = smem_u + FULL_OFF;
    const uint32_t emptyb = smem_u + EMPTY_OFF;

    const int og   = blockIdx.x & (OGROUPS - 1);   // 0..127
    const int half = blockIdx.x >> 7;              // 0..1
    const int b0 = half * BITERS;
    const int o0 = og * OW;

    const int tid  = threadIdx.x;
    const int w    = tid >> 5;
    const int lane = tid & 31;

    // ---- init barriers ----
    if (tid == 0) {
#pragma unroll
        for (int j = 0; j < STAGES; ++j) {
            mbar_init(fullb + 8u * j, 1);
            mbar_init(emptyb + 8u * j, OW);   // one arrive per consumer warp
        }
    }
    __syncthreads();   // the ONLY block-wide sync

    // ================= PRODUCER WARP (w == 8) =================
    if (w == 8) {
        if (lane == 0) {
            int st = 0, rnd = 0;
            for (int f = 0; f < BITERS; ++f) {
                if (rnd >= 1) {
                    mbar_wait(emptyb + 8u * st, (rnd - 1) & 1);
                    fence_async_smem();
                }
                const uint32_t mb = fullb + 8u * st;
                mbar_expect_tx(mb, STAGE_BYTES);
                const float* gsrc = gumbel + ((size_t)(b0 + f) * HH + o0) * HH;
                bulk_copy(smem_u + st * STAGE_BYTES, gsrc, STAGE_BYTES, mb);
                if (++st == STAGES) { st = 0; ++rnd; }
            }
        }
        return;
    }

    // ================= CONSUMER WARPS (w == 0..7) =================
    const int o = o0 + w;

    // per-warp constants, loaded ONCE per 32 tiles (overlaps prologue TMA)
    const float inv_tau_l2e = LOG2E / fmaxf(temperature[0], MIN_TAU);
    const float bias = b_ih[o];

    const float4* __restrict__ whr = reinterpret_cast<const float4*>(W_hh + (size_t)o * HH);
    float4 wp[8];
#pragma unroll
    for (int k = 0; k < 8; ++k) {
        float4 v = whr[lane + 32 * k];
        v.x *= inv_tau_l2e; v.y *= inv_tau_l2e;
        v.z *= inv_tau_l2e; v.w *= inv_tau_l2e;
        wp[k] = v;
    }
    const float4* __restrict__ wir = reinterpret_cast<const float4*>(W_ih + (size_t)o * II);
    float4 wih[4];
#pragma unroll
    for (int k = 0; k < 4; ++k) wih[k] = wir[lane + 32 * k];

    const float* __restrict__ rowbase = smem + (size_t)w * HH;

    int st = 0;
    int parity = 0;   // round parity: r = i/STAGES, parity = r&1
    for (int i = 0; i < BITERS; ++i) {
        const int b = b0 + i;

        // front-batched global loads (L2-resident; MLP 8+4) issued BEFORE
        // the full-wait so their latency hides under it.
        const float4* __restrict__ hr =
            reinterpret_cast<const float4*>(h_prev + (size_t)b * HH);
        float4 hv[8];
#pragma unroll
        for (int k = 0; k < 8; ++k) hv[k] = hr[lane + 32 * k];

        const float4* __restrict__ xr =
            reinterpret_cast<const float4*>(x_t + (size_t)b * II);
        float ic = 0.0f;
#pragma unroll
        for (int k = 0; k < 4; ++k) {
            const float4 xv = xr[lane + 32 * k];
            ic = fmaf(xv.x, wih[k].x, ic);
            ic = fmaf(xv.y, wih[k].y, ic);
            ic = fmaf(xv.z, wih[k].z, ic);
            ic = fmaf(xv.w, wih[k].w, ic);
        }

        mbar_wait(fullb + 8u * st, parity);

        const float4* __restrict__ gs = reinterpret_cast<const float4*>(
            rowbase + (size_t)st * (STAGE_BYTES / 4));

        float s = 0.0f, t = 0.0f;
#pragma unroll
        for (int k = 0; k < 8; ++k) {
            const float4 g = gs[lane + 32 * k];
            const float4 h = hv[k];
            float e;
            e = ex2(fmaf(g.x, LOG2E, wp[k].x)); s += e; t = fmaf(e, h.x, t);
            e = ex2(fmaf(g.y, LOG2E, wp[k].y)); s += e; t = fmaf(e, h.y, t);
            e = ex2(fmaf(g.z, LOG2E, wp[k].z)); s += e; t = fmaf(e, h.z, t);
            e = ex2(fmaf(g.w, LOG2E, wp[k].w)); s += e; t = fmaf(e, h.w, t);
        }

        // stage data consumed into registers: signal the producer, move on.
        __syncwarp();
        if (lane == 0) mbar_arrive(emptyb + 8u * st);

        // warp reductions + output (overlaps the producer's refill)
#pragma unroll
        for (int off = 16; off > 0; off >>= 1) {
            s  += __shfl_xor_sync(0xffffffffu, s,  off);
            t  += __shfl_xor_sync(0xffffffffu, t,  off);
            ic += __shfl_xor_sync(0xffffffffu, ic, off);
        }
        if (lane == 0) {
            out[(size_t)b * HH + o] = tanhf(ic + bias + t / s);
        }

        if (++st == STAGES) { st = 0; parity ^= 1; }
    }
}

extern "C" void kernel_launch(void* const* d_in, const int* in_sizes, int n_in,
                              void* d_out, int out_size) {
    // metadata order: x_t, h_prev, W_ih, b_ih, W_hh, temperature, gumbel_noise
    const float* x_t    = (const float*)d_in[0];
    const float* h_prev = (const float*)d_in[1];
    const float* W_ih   = (const float*)d_in[2];
    const float* b_ih   = (const float*)d_in[3];
    const float* W_hh   = (const float*)d_in[4];
    const float* temp   = (const float*)d_in[5];
    const float* gum    = (const float*)d_in[6];
    float* out = (float*)d_out;

    static bool attr_set = false;
    if (!attr_set) {
        cudaFuncSetAttribute(reservoir_cell_kernel,
                             cudaFuncAttributeMaxDynamicSharedMemorySize, SMEM_BYTES);
        attr_set = true;
    }

    dim3 grid(OGROUPS * HALVES);   // 128 * 2 = 256 CTAs: one resident wave
    dim3 block(NWARPS * 32);       // 288 threads: 8 consumer + 1 producer warp
    reservoir_cell_kernel<<<grid, block, SMEM_BYTES>>>(
        x_t, h_prev, W_ih, b_ih, W_hh, temp, gum, out);
}

// round 12
// speedup vs baseline: 1.3250x; 1.3224x over previous
#include <cuda_runtime.h>
#include <cstdint>

// Problem constants
#define BB 64
#define HH 1024
#define II 512
#define MIN_TAU 1e-3f
#define LOG2E 1.4426950408889634f

// Tiling: 256 resident CTAs (single wave on 148 SMs x 2 CTAs).
// CTA = fixed o-group of 8 rows x 32 b-iterations.
// 8 consumer warps + 1 dedicated producer warp = 288 threads.
#define OW 8
#define NWARPS 9
#define BITERS 32
#define OGROUPS (HH / OW)       // 128
#define HALVES (BB / BITERS)    // 2
#define STAGES 3

// SMEM layout (dynamic) — R9 proven: stage = 32KB gumbel + 4KB h_prev.
#define G_BYTES (OW * HH * 4)            // 32768
#define H_BYTES (HH * 4)                 // 4096
#define STAGE_BYTES (G_BYTES + H_BYTES)  // 36864
#define FULL_OFF (STAGES * STAGE_BYTES)
#define EMPTY_OFF (FULL_OFF + STAGES * 8)
#define SMEM_BYTES (EMPTY_OFF + STAGES * 8)  // 110640 -> 2 CTAs/SM

static __device__ __forceinline__ uint32_t s2u(const void* p) {
    uint32_t a;
    asm("{ .reg .u64 t; cvta.to.shared.u64 t, %1; cvt.u32.u64 %0, t; }"
        : "=r"(a) : "l"(p));
    return a;
}

static __device__ __forceinline__ void mbar_init(uint32_t mbar, uint32_t cnt) {
    asm volatile("mbarrier.init.shared.b64 [%0], %1;" :: "r"(mbar), "r"(cnt) : "memory");
}

static __device__ __forceinline__ void mbar_expect_tx(uint32_t mbar, uint32_t bytes) {
    asm volatile("mbarrier.arrive.expect_tx.shared.b64 _, [%0], %1;"
                 :: "r"(mbar), "r"(bytes) : "memory");
}

static __device__ __forceinline__ void mbar_arrive(uint32_t mbar) {
    asm volatile("mbarrier.arrive.release.cta.shared::cta.b64 _, [%0];"
                 :: "r"(mbar) : "memory");
}

static __device__ __forceinline__ void mbar_wait(uint32_t mbar, uint32_t parity) {
    uint32_t done;
    asm volatile(
        "{\n\t.reg .pred p;\n\t"
        "mbarrier.try_wait.parity.acquire.cta.shared::cta.b64 p, [%1], %2;\n\t"
        "selp.b32 %0, 1, 0, p;\n\t}"
        : "=r"(done) : "r"(mbar), "r"(parity) : "memory");
    if (!done) {
        asm volatile(
            "{\n\t.reg .pred P1;\n\t"
            "WL_%=:\n\t"
            "mbarrier.try_wait.parity.acquire.cta.shared::cta.b64 P1, [%0], %1, 0x989680;\n\t"
            "@P1 bra.uni WD_%=;\n\t"
            "bra.uni WL_%=;\n\t"
            "WD_%=:\n\t}"
            :: "r"(mbar), "r"(parity) : "memory");
    }
}

static __device__ __forceinline__ void bulk_copy(uint32_t dst_smem, const void* src,
                                                 uint32_t bytes, uint32_t mbar) {
    asm volatile(
        "cp.async.bulk.shared::cta.global.mbarrier::complete_tx::bytes [%0], [%1], %2, [%3];"
        :: "r"(dst_smem), "l"(src), "r"(bytes), "r"(mbar) : "memory");
}

static __device__ __forceinline__ void fence_async_smem() {
    asm volatile("fence.proxy.async.shared::cta;" ::: "memory");
}

static __device__ __forceinline__ float ex2(float x) {
    float y;
    asm("ex2.approx.ftz.f32 %0, %1;" : "=f"(y) : "f"(x));
    return y;
}

// Packed f32x2 helpers (sm_103a; PTX-only, ptxas never auto-fuses).
#define FMA_X2(d, a, b, c) \
    asm("fma.rn.f32x2 %0, %1, %2, %3;" : "=l"(d) : "l"(a), "l"(b), "l"(c))
#define ADD_X2(d, a, b) \
    asm("add.rn.f32x2 %0, %1, %2;" : "=l"(d) : "l"(a), "l"(b))
#define PACK_X2(d, lo, hi) \
    asm("mov.b64 %0, {%1, %2};" : "=l"(d) : "f"(lo), "f"(hi))
#define UNPACK_X2(lo, hi, s) \
    asm("mov.b64 {%0, %1}, %2;" : "=f"(lo), "=f"(hi) : "l"(s))

// Fused ReservoirRNNCell step — warp-specialized TMA pipeline (EXACT R9
// skeleton, 47.9us proven) + f32x2 packed consumer math:
//   grid = 256 CTAs (one wave at 2 CTAs/SM), 288 threads: warps 0-7 consume,
//   warp 8 produces. 3-stage ring; each fill = ONE 32KB bulk copy of
//   gumbel[b, o0:o0+8, :] + 4KB h_prev[b,:] (h_prev MUST ride the TMA
//   payload — LDG'ing it in the consumer loop couples L2 latency into the
//   empty-arrive path and drained the pipeline in R10/R11).
//   Consumer inner loop uses fma.rn.f32x2 / add.rn.f32x2: fma-pipe ops per
//   warp-iteration drop 96 -> 48; the pack/unpack mov.b64 around scalar EX2
//   are register-pair aliases (≈free in SASS).
// Softmax without max-subtraction is safe: logits bounded (~18.5);
// validated rel_err 3.4e-7 in R1-R11.
__global__ __launch_bounds__(288, 2) void reservoir_cell_kernel(
    const float* __restrict__ x_t,         // (B, I)
    const float* __restrict__ h_prev,      // (B, H)
    const float* __restrict__ W_ih,        // (H, I)
    const float* __restrict__ b_ih,        // (H,)
    const float* __restrict__ W_hh,        // (H, H)
    const float* __restrict__ temperature, // scalar
    const float* __restrict__ gumbel,      // (B, H, H)
    float* __restrict__ out)               // (B, H)
{
    extern __shared__ float smem[];
    const uint32_t smem_u = s2u(smem);
    const uint32_t fullb  = smem_u + FULL_OFF;
    const uint32_t emptyb = smem_u + EMPTY_OFF;

    const int og   = blockIdx.x & (OGROUPS - 1);   // 0..127
    const int half = blockIdx.x >> 7;              // 0..1
    const int b0 = half * BITERS;
    const int o0 = og * OW;

    const int tid  = threadIdx.x;
    const int w    = tid >> 5;
    const int lane = tid & 31;

    // ---- init barriers ----
    if (tid == 0) {
#pragma unroll
        for (int j = 0; j < STAGES; ++j) {
            mbar_init(fullb + 8u * j, 1);
            mbar_init(emptyb + 8u * j, OW);   // one arrive per consumer warp
        }
    }
    __syncthreads();   // the ONLY block-wide sync

    // ================= PRODUCER WARP (w == 8) =================
    if (w == 8) {
        if (lane == 0) {
            int st = 0, rnd = 0;
            for (int f = 0; f < BITERS; ++f) {
                if (rnd >= 1) {
                    mbar_wait(emptyb + 8u * st, (rnd - 1) & 1);
                    fence_async_smem();
                }
                const uint32_t mb = fullb + 8u * st;
                mbar_expect_tx(mb, STAGE_BYTES);
                const float* gsrc = gumbel + ((size_t)(b0 + f) * HH + o0) * HH;
                bulk_copy(smem_u + st * STAGE_BYTES, gsrc, G_BYTES, mb);
                const float* hsrc = h_prev + (size_t)(b0 + f) * HH;
                bulk_copy(smem_u + st * STAGE_BYTES + G_BYTES, hsrc, H_BYTES, mb);
                if (++st == STAGES) { st = 0; ++rnd; }
            }
        }
        return;
    }

    // ================= CONSUMER WARPS (w == 0..7) =================
    const int o = o0 + w;

    // per-warp constants, loaded ONCE per 32 tiles (overlaps prologue TMA):
    // W_hh row pre-scaled by inv_tau*log2e, stored as 16 packed f32x2 pairs.
    const float inv_tau_l2e = LOG2E / fmaxf(temperature[0], MIN_TAU);
    const float bias = b_ih[o];

    const float4* __restrict__ whr = reinterpret_cast<const float4*>(W_hh + (size_t)o * HH);
    uint64_t wp2[16];
#pragma unroll
    for (int k = 0; k < 8; ++k) {
        float4 v = whr[lane + 32 * k];
        PACK_X2(wp2[2 * k + 0], v.x * inv_tau_l2e, v.y * inv_tau_l2e);
        PACK_X2(wp2[2 * k + 1], v.z * inv_tau_l2e, v.w * inv_tau_l2e);
    }
    uint64_t l2e2;
    PACK_X2(l2e2, LOG2E, LOG2E);

    const float4* __restrict__ wir = reinterpret_cast<const float4*>(W_ih + (size_t)o * II);
    float4 wih[4];
#pragma unroll
    for (int k = 0; k < 4; ++k) wih[k] = wir[lane + 32 * k];

    int st = 0;
    int parity = 0;   // round parity: r = i/STAGES, parity = r&1
    for (int i = 0; i < BITERS; ++i) {
        const int b = b0 + i;

        // input contribution (register-cached W_ih) — overlaps the wait
        const float4* __restrict__ xr =
            reinterpret_cast<const float4*>(x_t + (size_t)b * II);
        float ic = 0.0f;
#pragma unroll
        for (int k = 0; k < 4; ++k) {
            const float4 xv = xr[lane + 32 * k];
            ic = fmaf(xv.x, wih[k].x, ic);
            ic = fmaf(xv.y, wih[k].y, ic);
            ic = fmaf(xv.z, wih[k].z, ic);
            ic = fmaf(xv.w, wih[k].w, ic);
        }

        mbar_wait(fullb + 8u * st, parity);

        const float4* __restrict__ gs = reinterpret_cast<const float4*>(
            smem + (size_t)st * (STAGE_BYTES / 4) + (size_t)w * HH);
        const float4* __restrict__ hs = reinterpret_cast<const float4*>(
            smem + (size_t)st * (STAGE_BYTES / 4) + G_BYTES / 4);

        uint64_t s2 = 0, t2 = 0;   // packed (f32x2) accumulators, both lanes 0.0f
#pragma unroll
        for (int k = 0; k < 8; ++k) {
            const int idx = lane + 32 * k;
            const float4 g = gs[idx];
            const float4 h = hs[idx];

            uint64_t g01, g23, h01, h23;
            PACK_X2(g01, g.x, g.y);  PACK_X2(g23, g.z, g.w);
            PACK_X2(h01, h.x, h.y);  PACK_X2(h23, h.z, h.w);

            uint64_t l01, l23;
            FMA_X2(l01, g01, l2e2, wp2[2 * k + 0]);   // logit*log2e, packed
            FMA_X2(l23, g23, l2e2, wp2[2 * k + 1]);

            float a0, a1, a2, a3;
            UNPACK_X2(a0, a1, l01);
            UNPACK_X2(a2, a3, l23);
            const float e0 = ex2(a0), e1 = ex2(a1);
            const float e2 = ex2(a2), e3 = ex2(a3);

            uint64_t e01, e23;
            PACK_X2(e01, e0, e1);
            PACK_X2(e23, e2, e3);

            ADD_X2(s2, s2, e01);
            ADD_X2(s2, s2, e23);
            FMA_X2(t2, e01, h01, t2);
            FMA_X2(t2, e23, h23, t2);
        }

        // stage data consumed into registers: signal the producer, move on.
        __syncwarp();
        if (lane == 0) mbar_arrive(emptyb + 8u * st);

        // fold packed accumulators, then warp reductions + output
        float sl, sh, tl, th;
        UNPACK_X2(sl, sh, s2);
        UNPACK_X2(tl, th, t2);
        float s = sl + sh;
        float t = tl + th;
#pragma unroll
        for (int off = 16; off > 0; off >>= 1) {
            s  += __shfl_xor_sync(0xffffffffu, s,  off);
            t  += __shfl_xor_sync(0xffffffffu, t,  off);
            ic += __shfl_xor_sync(0xffffffffu, ic, off);
        }
        if (lane == 0) {
            out[(size_t)b * HH + o] = tanhf(ic + bias + t / s);
        }

        if (++st == STAGES) { st = 0; parity ^= 1; }
    }
}

extern "C" void kernel_launch(void* const* d_in, const int* in_sizes, int n_in,
                              void* d_out, int out_size) {
    // metadata order: x_t, h_prev, W_ih, b_ih, W_hh, temperature, gumbel_noise
    const float* x_t    = (const float*)d_in[0];
    const float* h_prev = (const float*)d_in[1];
    const float* W_ih   = (const float*)d_in[2];
    const float* b_ih   = (const float*)d_in[3];
    const float* W_hh   = (const float*)d_in[4];
    const float* temp   = (const float*)d_in[5];
    const float* gum    = (const float*)d_in[6];
    float* out = (float*)d_out;

    static bool attr_set = false;
    if (!attr_set) {
        cudaFuncSetAttribute(reservoir_cell_kernel,
                             cudaFuncAttributeMaxDynamicSharedMemorySize, SMEM_BYTES);
        attr_set = true;
    }

    dim3 grid(OGROUPS * HALVES);   // 128 * 2 = 256 CTAs: one resident wave
    dim3 block(NWARPS * 32);       // 288 threads: 8 consumer + 1 producer warp
    reservoir_cell_kernel<<<grid, block, SMEM_BYTES>>>(
        x_t, h_prev, W_ih, b_ih, W_hh, temp, gum, out);
}